// round 14
// baseline (speedup 1.0000x reference)
#include <cuda_runtime.h>
#include <cuda_bf16.h>
#include <cuda_fp16.h>
#include <math.h>
#include <stdint.h>

// ---------------------------------------------------------------------------
// T2T-ViT forward. B=64, N=197, C=768, D=12, H=12, dk=64, F=3072, V=1000.
// GEMMs: mma.sync m16n8k16 bf16, 3-MMA hi/lo split, ldmatrix consumer with
// hi/lo-merged x4 for B, pre-split bf16 planes, BK=32 double-buffer with
// interleaved 16-reg LDG/STS halves, col-major grid, 2 CTAs/SM.
// Attention: fp16 K/V smem, 2 rows/thread.
// ---------------------------------------------------------------------------

#define BB   64
#define NN   197
#define CC   768
#define TT   (BB * NN)        // 12608
#define MP   12672            // 99*128
#define HH   12
#define DK   64
#define FF   3072
#define NL   12
#define VV   1000

// GEMM smem: 2 buffers x 4 planes x (128 rows x 80B)  (BK=32 bf16 = 64B + 16 pad)
#define PLANEB   10240
#define STAGEB   40960
#define GB_SMEM  (2 * STAGEB)   // 81920

#define ATT_SMEM (NN * DK * 2 * 2)     // 50432 B (fp16 K + V)

// --------------------------- scratch (static device) -------------------------
__device__ float g_h  [MP * CC];
__device__ float g_qkv[MP * 3 * CC];
__device__ float g_cls[BB * CC];

__device__ __nv_bfloat16 g_yh[MP * CC],  g_yl[MP * CC];
__device__ __nv_bfloat16 g_oh[MP * CC],  g_ol[MP * CC];
__device__ __nv_bfloat16 g_mh[MP * FF],  g_ml[MP * FF];

#define W_QKV (NL * 3 * CC * CC)
#define W_PRJ (NL * CC * CC)
#define W_FC1 (NL * FF * CC)
#define W_FC2 (NL * CC * FF)
__device__ __nv_bfloat16 g_wqh[W_QKV], g_wql[W_QKV];
__device__ __nv_bfloat16 g_wph[W_PRJ], g_wpl[W_PRJ];
__device__ __nv_bfloat16 g_w1h[W_FC1], g_w1l[W_FC1];
__device__ __nv_bfloat16 g_w2h[W_FC2], g_w2l[W_FC2];

// --------------------------- helpers ----------------------------------------
__device__ __forceinline__ uint32_t cvt_bf16x2(float a, float b) {
    uint32_t r;
    asm("cvt.rn.bf16x2.f32 %0, %2, %1;" : "=r"(r) : "f"(a), "f"(b));
    return r;
}
__device__ __forceinline__ void split2(float a, float b, uint32_t& h, uint32_t& l) {
    h = cvt_bf16x2(a, b);
    float ha = __uint_as_float(h << 16);
    float hb = __uint_as_float(h & 0xffff0000u);
    l = cvt_bf16x2(a - ha, b - hb);
}
__device__ __forceinline__ void split4(float4 v, uint32_t& h01, uint32_t& h23,
                                       uint32_t& l01, uint32_t& l23) {
    split2(v.x, v.y, h01, l01);
    split2(v.z, v.w, h23, l23);
}
__device__ __forceinline__ float gelu_exact(float f) {
    return 0.5f * f * (1.0f + erff(f * 0.70710678118654752f));
}
__device__ __forceinline__ void mma16816(float* d, const uint32_t* a,
                                         uint32_t b0, uint32_t b1) {
    asm volatile(
        "mma.sync.aligned.m16n8k16.row.col.f32.bf16.bf16.f32 "
        "{%0,%1,%2,%3}, {%4,%5,%6,%7}, {%8,%9}, {%0,%1,%2,%3};"
        : "+f"(d[0]), "+f"(d[1]), "+f"(d[2]), "+f"(d[3])
        : "r"(a[0]), "r"(a[1]), "r"(a[2]), "r"(a[3]), "r"(b0), "r"(b1));
}
__device__ __forceinline__ void ldsm_x4(uint32_t* r, uint32_t addr) {
    asm volatile("ldmatrix.sync.aligned.m8n8.x4.shared.b16 {%0,%1,%2,%3}, [%4];"
        : "=r"(r[0]), "=r"(r[1]), "=r"(r[2]), "=r"(r[3]) : "r"(addr));
}
__device__ __forceinline__ uint32_t smem_u32(const void* p) {
    uint32_t a;
    asm("{ .reg .u64 t; cvta.to.shared.u64 t, %1; cvt.u32.u64 %0, t; }"
        : "=r"(a) : "l"(p));
    return a;
}

// --------------------------- weight split kernel -----------------------------
__global__ void conv_kernel(const float4* __restrict__ w,
                            uint2* __restrict__ wh, uint2* __restrict__ wl,
                            int n4)
{
    for (int i = blockIdx.x * blockDim.x + threadIdx.x; i < n4;
         i += gridDim.x * blockDim.x) {
        float4 v = w[i];
        uint32_t h01, h23, l01, l23;
        split4(v, h01, h23, l01, l23);
        wh[i] = make_uint2(h01, h23);
        wl[i] = make_uint2(l01, l23);
    }
}

// --------------------------- bf16-split GEMM (interleaved dbl-buffer) --------
// out[M,Nd] = A[M,K] @ W[Nd,K]^T (+bias, gelu, res). Planes pre-split hi/lo.
// Block 128x128, BK=32, 256 thr (8 warps, warp tile 64x32), double smem buffer.
// B fragments via hi/lo-merged ldmatrix.x4 (lanes 0-15 hi, 16-31 lo plane).
// Per stage: ldg(A,s+1) | MMA k16#0 | sts(A)+ldg(B,s+1) | MMA k16#1 | sts(B) | bar.
// grid = (Nd/128, M/128) col-major.
template<bool BIAS, bool GELU, bool RES, bool OUTBF>
__global__ __launch_bounds__(256, 2)
void gemm_bf(const __nv_bfloat16* __restrict__ Ah, const __nv_bfloat16* __restrict__ Al,
             const __nv_bfloat16* __restrict__ Bh, const __nv_bfloat16* __restrict__ Bl,
             const float* __restrict__ bias, const float* __restrict__ res,
             float* __restrict__ out,
             __nv_bfloat16* __restrict__ outh, __nv_bfloat16* __restrict__ outl,
             int M, int Nd, int K)
{
    extern __shared__ char smem[];
    uint32_t sb = smem_u32(smem);
    const int tid = threadIdx.x, wid = tid >> 5, lane = tid & 31;
    const int n0 = blockIdx.x * 128, m0 = blockIdx.y * 128;
    const int warp_m = wid & 1, warp_n = wid >> 1;
    const int g = lane >> 2, t = lane & 3;
    const int l16 = lane & 15;

    // ldmatrix lane-address bases (byte offsets within plane, stride 80)
    const uint32_t aOff = (uint32_t)((warp_m * 64 + (lane & 15)) * 80
                                     + ((lane >> 4) << 4));
    // merged B: lanes 0-15 hi plane, lanes 16-31 same offsets in lo plane
    const uint32_t bOff = (uint32_t)((warp_n * 32 + (l16 & 7)) * 80
                                     + ((l16 & 8) << 1)
                                     + ((lane >> 4) ? PLANEB : 0));

    float acc[4][4][4];
    #pragma unroll
    for (int i = 0; i < 4; i++)
        #pragma unroll
        for (int j = 0; j < 4; j++)
            #pragma unroll
            for (int e = 0; e < 4; e++) acc[i][j][e] = 0.f;

    const int NS = K / 32;
    const __nv_bfloat16* sA0 = Ah + (size_t)m0 * K;
    const __nv_bfloat16* sA1 = Al + (size_t)m0 * K;
    const __nv_bfloat16* sB0 = Bh + (size_t)n0 * K;
    const __nv_bfloat16* sB1 = Bl + (size_t)n0 * K;

    const int r0 = tid >> 2, r1 = (tid >> 2) + 64;
    const int lch = tid & 3;

    uint4 pf[4];   // one half (2 planes x 2 rows) at a time = 16 regs

    auto ldgA = [&](int s) {
        const int k0 = s * 32 + lch * 8;
        pf[0] = *(const uint4*)(sA0 + (size_t)r0 * K + k0);
        pf[1] = *(const uint4*)(sA0 + (size_t)r1 * K + k0);
        pf[2] = *(const uint4*)(sA1 + (size_t)r0 * K + k0);
        pf[3] = *(const uint4*)(sA1 + (size_t)r1 * K + k0);
    };
    auto ldgB = [&](int s) {
        const int k0 = s * 32 + lch * 8;
        pf[0] = *(const uint4*)(sB0 + (size_t)r0 * K + k0);
        pf[1] = *(const uint4*)(sB0 + (size_t)r1 * K + k0);
        pf[2] = *(const uint4*)(sB1 + (size_t)r0 * K + k0);
        pf[3] = *(const uint4*)(sB1 + (size_t)r1 * K + k0);
    };
    auto stsA = [&](int buf) {
        char* st = smem + buf * STAGEB + lch * 16;
        *(uint4*)(st + r0 * 80)          = pf[0];
        *(uint4*)(st + r1 * 80)          = pf[1];
        *(uint4*)(st + PLANEB + r0 * 80) = pf[2];
        *(uint4*)(st + PLANEB + r1 * 80) = pf[3];
    };
    auto stsB = [&](int buf) {
        char* st = smem + buf * STAGEB + 2 * PLANEB + lch * 16;
        *(uint4*)(st + r0 * 80)          = pf[0];
        *(uint4*)(st + r1 * 80)          = pf[1];
        *(uint4*)(st + PLANEB + r0 * 80) = pf[2];
        *(uint4*)(st + PLANEB + r1 * 80) = pf[3];
    };

    // preload stage 0 into buffer 0
    ldgA(0); stsA(0);
    ldgB(0); stsB(0);
    __syncthreads();

    for (int s = 0; s < NS; s++) {
        const int buf = s & 1, nxt = buf ^ 1;
        const uint32_t base = sb + buf * STAGEB;
        const uint32_t aH = base + aOff, aL = aH + PLANEB;
        const uint32_t bB = base + 2 * PLANEB + bOff;
        const bool more = (s + 1 < NS);

        if (more) ldgA(s + 1);

        // ---- k16 block #0 (kb = 0) ----
        {
            const uint32_t kb = 0;
            uint32_t bf[4][4];
            #pragma unroll
            for (int j = 0; j < 4; j++)
                ldsm_x4(bf[j], bB + (uint32_t)(j * 8 * 80) + kb);
            #pragma unroll
            for (int i = 0; i < 4; i++) {
                uint32_t ah[4], al[4];
                ldsm_x4(ah, aH + (uint32_t)(i * 16 * 80) + kb);
                ldsm_x4(al, aL + (uint32_t)(i * 16 * 80) + kb);
                #pragma unroll
                for (int j = 0; j < 4; j++) {
                    mma16816(acc[i][j], ah, bf[j][0], bf[j][1]);
                    mma16816(acc[i][j], ah, bf[j][2], bf[j][3]);
                    mma16816(acc[i][j], al, bf[j][0], bf[j][1]);
                }
            }
        }

        if (more) { stsA(nxt); ldgB(s + 1); }

        // ---- k16 block #1 (kb = 32) ----
        {
            const uint32_t kb = 32;
            uint32_t bf[4][4];
            #pragma unroll
            for (int j = 0; j < 4; j++)
                ldsm_x4(bf[j], bB + (uint32_t)(j * 8 * 80) + kb);
            #pragma unroll
            for (int i = 0; i < 4; i++) {
                uint32_t ah[4], al[4];
                ldsm_x4(ah, aH + (uint32_t)(i * 16 * 80) + kb);
                ldsm_x4(al, aL + (uint32_t)(i * 16 * 80) + kb);
                #pragma unroll
                for (int j = 0; j < 4; j++) {
                    mma16816(acc[i][j], ah, bf[j][0], bf[j][1]);
                    mma16816(acc[i][j], ah, bf[j][2], bf[j][3]);
                    mma16816(acc[i][j], al, bf[j][0], bf[j][1]);
                }
            }
        }

        if (more) stsB(nxt);
        __syncthreads();
    }

    // ---- epilogue ------------------------------------------------------------
    #pragma unroll
    for (int i = 0; i < 4; i++) {
        #pragma unroll
        for (int j = 0; j < 4; j++) {
            int gm0 = m0 + warp_m * 64 + i * 16 + g;
            int gn  = n0 + warp_n * 32 + j * 8 + 2 * t;
            #pragma unroll
            for (int half = 0; half < 2; half++) {
                int gm = gm0 + half * 8;
                float v0 = acc[i][j][half * 2 + 0];
                float v1 = acc[i][j][half * 2 + 1];
                if (BIAS) { v0 += bias[gn]; v1 += bias[gn + 1]; }
                if (GELU) { v0 = gelu_exact(v0); v1 = gelu_exact(v1); }
                if (OUTBF) {
                    uint32_t h01, l01;
                    split2(v0, v1, h01, l01);
                    *(uint32_t*)(outh + (size_t)gm * Nd + gn) = h01;
                    *(uint32_t*)(outl + (size_t)gm * Nd + gn) = l01;
                } else {
                    if (RES) {
                        float2 r2 = *(const float2*)(res + (size_t)gm * Nd + gn);
                        v0 += r2.x; v1 += r2.y;
                    }
                    *(float2*)(out + (size_t)gm * Nd + gn) = make_float2(v0, v1);
                }
            }
        }
    }
}

// --------------------------- embed (pads zeroed) ------------------------------
__global__ void embed_kernel(const float* __restrict__ x,
                             const float* __restrict__ cls,
                             float* __restrict__ h)
{
    int row = blockIdx.x;
    if (row >= TT) {
        for (int c = threadIdx.x; c < CC; c += blockDim.x)
            h[(size_t)row * CC + c] = 0.f;
        return;
    }
    int b = row / NN, n = row % NN;
    for (int c = threadIdx.x; c < CC; c += blockDim.x) {
        float base = (n == 0) ? cls[c]
                              : x[((size_t)b * (NN - 1) + (n - 1)) * CC + c];
        int jj = c & ~1;
        float div = __expf(-9.210340371976184f * (float)jj / 768.0f);
        float ang = (float)n * div;
        float pe  = (c & 1) ? cosf(ang) : sinf(ang);
        h[(size_t)row * CC + c] = base + pe;
    }
}

// --------------------------- layernorm ----------------------------------------
template<bool OUTBF>
__global__ void ln_kernel(const float* __restrict__ x,
                          const float* __restrict__ w,
                          const float* __restrict__ bns,
                          float* __restrict__ yf,
                          __nv_bfloat16* __restrict__ yh,
                          __nv_bfloat16* __restrict__ yl,
                          int in_row_stride)
{
    const float* xr = x + (size_t)blockIdx.x * in_row_stride * CC;
    int t = threadIdx.x;
    float v0 = xr[t], v1 = xr[t + 256], v2 = xr[t + 512];
    float s = v0 + v1 + v2;
    float q = v0 * v0 + v1 * v1 + v2 * v2;
    #pragma unroll
    for (int o = 16; o; o >>= 1) {
        s += __shfl_xor_sync(0xffffffffu, s, o);
        q += __shfl_xor_sync(0xffffffffu, q, o);
    }
    __shared__ float ss[8], qs[8];
    if ((t & 31) == 0) { ss[t >> 5] = s; qs[t >> 5] = q; }
    __syncthreads();
    float tot = 0.f, totq = 0.f;
    #pragma unroll
    for (int i = 0; i < 8; i++) { tot += ss[i]; totq += qs[i]; }
    float mu   = tot * (1.0f / 768.0f);
    float var  = totq * (1.0f / 768.0f) - mu * mu;
    float rstd = rsqrtf(var + 1e-5f);
    float r0 = (v0 - mu) * rstd * w[t]       + bns[t];
    float r1 = (v1 - mu) * rstd * w[t + 256] + bns[t + 256];
    float r2 = (v2 - mu) * rstd * w[t + 512] + bns[t + 512];
    if (OUTBF) {
        size_t base = (size_t)blockIdx.x * CC;
        __nv_bfloat16 h0 = __float2bfloat16(r0);
        __nv_bfloat16 h1 = __float2bfloat16(r1);
        __nv_bfloat16 h2 = __float2bfloat16(r2);
        yh[base + t]       = h0;
        yh[base + t + 256] = h1;
        yh[base + t + 512] = h2;
        yl[base + t]       = __float2bfloat16(r0 - __bfloat162float(h0));
        yl[base + t + 256] = __float2bfloat16(r1 - __bfloat162float(h1));
        yl[base + t + 512] = __float2bfloat16(r2 - __bfloat162float(h2));
    } else {
        float* yr = yf + (size_t)blockIdx.x * CC;
        yr[t] = r0; yr[t + 256] = r1; yr[t + 512] = r2;
    }
}

// --------------------------- fused attention ----------------------------------
// fp16 K/V in smem (fp32 math), 2 query rows per thread. grid (B*H, 2).
__global__ __launch_bounds__(256, 2)
void attn_kernel(const float* __restrict__ qkv,
                 __nv_bfloat16* __restrict__ oh,
                 __nv_bfloat16* __restrict__ ol)
{
    extern __shared__ __half smh[];
    __half* Ks = smh;               // NN*DK
    __half* Vs = smh + NN * DK;
    int bh = blockIdx.x;
    int b = bh / HH, h = bh % HH;
    const float* base = qkv + (size_t)b * NN * (3 * CC);

    for (int idx = threadIdx.x; idx < (NN * DK) / 4; idx += 256) {
        int row = idx >> 4, d4 = (idx & 15) << 2;
        float4 kv = *(const float4*)(base + (size_t)row * (3 * CC) +     CC + h * DK + d4);
        float4 vv = *(const float4*)(base + (size_t)row * (3 * CC) + 2 * CC + h * DK + d4);
        *(__half2*)(Ks + row * DK + d4)     = __floats2half2_rn(kv.x, kv.y);
        *(__half2*)(Ks + row * DK + d4 + 2) = __floats2half2_rn(kv.z, kv.w);
        *(__half2*)(Vs + row * DK + d4)     = __floats2half2_rn(vv.x, vv.y);
        *(__half2*)(Vs + row * DK + d4 + 2) = __floats2half2_rn(vv.z, vv.w);
    }
    __syncthreads();

    int grp = threadIdx.x >> 2, sub = threadIdx.x & 3;
    int r0 = blockIdx.y * 128 + grp;
    int r1 = r0 + 64;
    int c0 = (r0 < NN) ? r0 : NN - 1;
    int c1 = (r1 < NN) ? r1 : NN - 1;

    float q0[16], q1[16];
    {
        const float* qp0 = base + (size_t)c0 * (3 * CC) + h * DK + sub * 16;
        const float* qp1 = base + (size_t)c1 * (3 * CC) + h * DK + sub * 16;
        #pragma unroll
        for (int k = 0; k < 16; k += 4) {
            float4 v = *(const float4*)(qp0 + k);
            q0[k] = v.x * 0.125f; q0[k+1] = v.y * 0.125f;
            q0[k+2] = v.z * 0.125f; q0[k+3] = v.w * 0.125f;
            float4 w = *(const float4*)(qp1 + k);
            q1[k] = w.x * 0.125f; q1[k+1] = w.y * 0.125f;
            q1[k+2] = w.z * 0.125f; q1[k+3] = w.w * 0.125f;
        }
    }

    float mx0 = -1e30f, l0 = 0.f, mx1 = -1e30f, l1 = 0.f;
    float acc0[16], acc1[16];
    #pragma unroll
    for (int k = 0; k < 16; k++) { acc0[k] = 0.f; acc1[k] = 0.f; }

    for (int j = 0; j < NN; j++) {
        const __half* kr = Ks + j * DK + sub * 16;
        float kf[16];
        {
            uint4 u0 = *(const uint4*)(kr);
            uint4 u1 = *(const uint4*)(kr + 8);
            const uint32_t* uw = &u0.x;
            #pragma unroll
            for (int e = 0; e < 4; e++) {
                float2 f = __half22float2(*(const __half2*)&uw[e]);
                kf[e * 2] = f.x; kf[e * 2 + 1] = f.y;
            }
            const uint32_t* uw1 = &u1.x;
            #pragma unroll
            for (int e = 0; e < 4; e++) {
                float2 f = __half22float2(*(const __half2*)&uw1[e]);
                kf[8 + e * 2] = f.x; kf[8 + e * 2 + 1] = f.y;
            }
        }
        float s0 = 0.f, s1 = 0.f;
        #pragma unroll
        for (int k = 0; k < 16; k++) { s0 += q0[k] * kf[k]; s1 += q1[k] * kf[k]; }
        s0 += __shfl_xor_sync(0xffffffffu, s0, 1);
        s0 += __shfl_xor_sync(0xffffffffu, s0, 2);
        s1 += __shfl_xor_sync(0xffffffffu, s1, 1);
        s1 += __shfl_xor_sync(0xffffffffu, s1, 2);

        if (s0 > mx0) {
            float cr = __expf(mx0 - s0);
            l0 *= cr;
            #pragma unroll
            for (int k = 0; k < 16; k++) acc0[k] *= cr;
            mx0 = s0;
        }
        float p0 = __expf(s0 - mx0);
        l0 += p0;
        if (s1 > mx1) {
            float cr = __expf(mx1 - s1);
            l1 *= cr;
            #pragma unroll
            for (int k = 0; k < 16; k++) acc1[k] *= cr;
            mx1 = s1;
        }
        float p1 = __expf(s1 - mx1);
        l1 += p1;

        const __half* vr = Vs + j * DK + sub * 16;
        uint4 w0 = *(const uint4*)(vr);
        uint4 w1 = *(const uint4*)(vr + 8);
        const uint32_t* vw0 = &w0.x;
        const uint32_t* vw1 = &w1.x;
        #pragma unroll
        for (int e = 0; e < 4; e++) {
            float2 f = __half22float2(*(const __half2*)&vw0[e]);
            acc0[e*2]   += p0 * f.x; acc0[e*2+1] += p0 * f.y;
            acc1[e*2]   += p1 * f.x; acc1[e*2+1] += p1 * f.y;
            float2 g2 = __half22float2(*(const __half2*)&vw1[e]);
            acc0[8+e*2]   += p0 * g2.x; acc0[8+e*2+1] += p0 * g2.y;
            acc1[8+e*2]   += p1 * g2.x; acc1[8+e*2+1] += p1 * g2.y;
        }
    }

    if (r0 < NN) {
        float inv = 1.0f / l0;
        size_t off = (size_t)(b * NN + r0) * CC + h * DK + sub * 16;
        #pragma unroll
        for (int k = 0; k < 16; k += 2) {
            uint32_t h01, l01;
            split2(acc0[k] * inv, acc0[k + 1] * inv, h01, l01);
            *(uint32_t*)(oh + off + k) = h01;
            *(uint32_t*)(ol + off + k) = l01;
        }
    }
    if (r1 < NN) {
        float inv = 1.0f / l1;
        size_t off = (size_t)(b * NN + r1) * CC + h * DK + sub * 16;
        #pragma unroll
        for (int k = 0; k < 16; k += 2) {
            uint32_t h01, l01;
            split2(acc1[k] * inv, acc1[k + 1] * inv, h01, l01);
            *(uint32_t*)(oh + off + k) = h01;
            *(uint32_t*)(ol + off + k) = l01;
        }
    }
}

// --------------------------- small SIMT GEMM (head) ---------------------------
template<bool BIAS>
__global__ void gemm_nt(const float* __restrict__ A, const float* __restrict__ W,
                        const float* __restrict__ bias, float* __restrict__ out,
                        int M, int Nd, int K)
{
    const int BM = 128, BN = 128, BK = 8;
    __shared__ float As[BK][BM + 4];
    __shared__ float Ws[BK][BN + 4];
    int t = threadIdx.x, tx = t & 15, ty = t >> 4;
    int m0 = blockIdx.x * BM, n0 = blockIdx.y * BN;
    int lrow = t >> 1, lk = (t & 1) * 4;
    float acc[8][8];
    #pragma unroll
    for (int i = 0; i < 8; i++)
        #pragma unroll
        for (int j = 0; j < 8; j++) acc[i][j] = 0.f;
    for (int k0 = 0; k0 < K; k0 += BK) {
        int gm = m0 + lrow;
        float4 va = (gm < M) ? *(const float4*)(A + (size_t)gm * K + k0 + lk)
                             : make_float4(0,0,0,0);
        As[lk+0][lrow]=va.x; As[lk+1][lrow]=va.y; As[lk+2][lrow]=va.z; As[lk+3][lrow]=va.w;
        int gn = n0 + lrow;
        float4 vw = (gn < Nd) ? *(const float4*)(W + (size_t)gn * K + k0 + lk)
                              : make_float4(0,0,0,0);
        Ws[lk+0][lrow]=vw.x; Ws[lk+1][lrow]=vw.y; Ws[lk+2][lrow]=vw.z; Ws[lk+3][lrow]=vw.w;
        __syncthreads();
        #pragma unroll
        for (int k = 0; k < BK; k++) {
            float ra[8], rb[8];
            *(float4*)(ra)   = *(const float4*)&As[k][ty*8];
            *(float4*)(ra+4) = *(const float4*)&As[k][ty*8+4];
            *(float4*)(rb)   = *(const float4*)&Ws[k][tx*8];
            *(float4*)(rb+4) = *(const float4*)&Ws[k][tx*8+4];
            #pragma unroll
            for (int i = 0; i < 8; i++)
                #pragma unroll
                for (int j = 0; j < 8; j++) acc[i][j] += ra[i] * rb[j];
        }
        __syncthreads();
    }
    #pragma unroll
    for (int i = 0; i < 8; i++) {
        int gm = m0 + ty * 8 + i;
        if (gm >= M) continue;
        #pragma unroll
        for (int j = 0; j < 8; j++) {
            int gn = n0 + tx * 8 + j;
            if (gn >= Nd) continue;
            float v = acc[i][j];
            if (BIAS) v += bias[gn];
            out[(size_t)gm * Nd + gn] = v;
        }
    }
}

// ---------------------------------------------------------------------------
extern "C" void kernel_launch(void* const* d_in, const int* in_sizes, int n_in,
                              void* d_out, int out_size)
{
    const float* x      = (const float*)d_in[0];
    const float* cls    = (const float*)d_in[1];
    const float* qkv_w  = (const float*)d_in[2];
    const float* proj_w = (const float*)d_in[3];
    const float* proj_b = (const float*)d_in[4];
    const float* ln1_w  = (const float*)d_in[5];
    const float* ln1_b  = (const float*)d_in[6];
    const float* ln2_w  = (const float*)d_in[7];
    const float* ln2_b  = (const float*)d_in[8];
    const float* fc1_w  = (const float*)d_in[9];
    const float* fc1_b  = (const float*)d_in[10];
    const float* fc2_w  = (const float*)d_in[11];
    const float* fc2_b  = (const float*)d_in[12];
    const float* norm_w = (const float*)d_in[13];
    const float* norm_b = (const float*)d_in[14];
    const float* head_w = (const float*)d_in[15];
    const float* head_b = (const float*)d_in[16];
    float* out = (float*)d_out;

    float *ph, *pqkv, *pcls;
    __nv_bfloat16 *pyh, *pyl, *poh, *pol, *pmh, *pml;
    __nv_bfloat16 *pwqh, *pwql, *pwph, *pwpl, *pw1h, *pw1l, *pw2h, *pw2l;
    cudaGetSymbolAddress((void**)&ph,   g_h);
    cudaGetSymbolAddress((void**)&pqkv, g_qkv);
    cudaGetSymbolAddress((void**)&pcls, g_cls);
    cudaGetSymbolAddress((void**)&pyh, g_yh);  cudaGetSymbolAddress((void**)&pyl, g_yl);
    cudaGetSymbolAddress((void**)&poh, g_oh);  cudaGetSymbolAddress((void**)&pol, g_ol);
    cudaGetSymbolAddress((void**)&pmh, g_mh);  cudaGetSymbolAddress((void**)&pml, g_ml);
    cudaGetSymbolAddress((void**)&pwqh, g_wqh); cudaGetSymbolAddress((void**)&pwql, g_wql);
    cudaGetSymbolAddress((void**)&pwph, g_wph); cudaGetSymbolAddress((void**)&pwpl, g_wpl);
    cudaGetSymbolAddress((void**)&pw1h, g_w1h); cudaGetSymbolAddress((void**)&pw1l, g_w1l);
    cudaGetSymbolAddress((void**)&pw2h, g_w2h); cudaGetSymbolAddress((void**)&pw2l, g_w2l);

    cudaFuncSetAttribute(attn_kernel,
                         cudaFuncAttributeMaxDynamicSharedMemorySize, ATT_SMEM);
    cudaFuncSetAttribute(gemm_bf<false,false,false,false>,
                         cudaFuncAttributeMaxDynamicSharedMemorySize, GB_SMEM);
    cudaFuncSetAttribute(gemm_bf<true,false,true,false>,
                         cudaFuncAttributeMaxDynamicSharedMemorySize, GB_SMEM);
    cudaFuncSetAttribute(gemm_bf<true,true,false,true>,
                         cudaFuncAttributeMaxDynamicSharedMemorySize, GB_SMEM);

    const int MTT = MP / 128;  // 99

    // Launch order keeps the first QKV gemm at launch #4 for the profiler.
    conv_kernel<<<1184, 256>>>((const float4*)qkv_w, (uint2*)pwqh, (uint2*)pwql, W_QKV/4);
    embed_kernel<<<MP, 256>>>(x, cls, ph);
    ln_kernel<true><<<TT, 256>>>(ph, ln1_w, ln1_b, nullptr, pyh, pyl, 1);
    gemm_bf<false,false,false,false><<<dim3((3*CC)/128, MTT), 256, GB_SMEM>>>(
        pyh, pyl, pwqh, pwql, nullptr, nullptr, pqkv, nullptr, nullptr,
        MP, 3*CC, CC);
    conv_kernel<<<1184, 256>>>((const float4*)proj_w, (uint2*)pwph, (uint2*)pwpl, W_PRJ/4);
    conv_kernel<<<1184, 256>>>((const float4*)fc1_w, (uint2*)pw1h, (uint2*)pw1l, W_FC1/4);
    conv_kernel<<<1184, 256>>>((const float4*)fc2_w, (uint2*)pw2h, (uint2*)pw2l, W_FC2/4);

    for (int d = 0; d < NL; d++) {
        const __nv_bfloat16* qwh = pwqh + (size_t)d * 3 * CC * CC;
        const __nv_bfloat16* qwl = pwql + (size_t)d * 3 * CC * CC;
        const __nv_bfloat16* pwh = pwph + (size_t)d * CC * CC;
        const __nv_bfloat16* pwl = pwpl + (size_t)d * CC * CC;
        const __nv_bfloat16* w1h = pw1h + (size_t)d * FF * CC;
        const __nv_bfloat16* w1l = pw1l + (size_t)d * FF * CC;
        const __nv_bfloat16* w2h = pw2h + (size_t)d * CC * FF;
        const __nv_bfloat16* w2l = pw2l + (size_t)d * CC * FF;
        const float* pb  = proj_b + (size_t)d * CC;
        const float* l2w = ln2_w  + (size_t)d * CC;
        const float* l2b = ln2_b  + (size_t)d * CC;
        const float* f1b = fc1_b  + (size_t)d * FF;
        const float* f2b = fc2_b  + (size_t)d * CC;

        if (d > 0) {
            const float* l1w = ln1_w + (size_t)d * CC;
            const float* l1b = ln1_b + (size_t)d * CC;
            ln_kernel<true><<<TT, 256>>>(ph, l1w, l1b, nullptr, pyh, pyl, 1);
            gemm_bf<false,false,false,false><<<dim3((3*CC)/128, MTT), 256, GB_SMEM>>>(
                pyh, pyl, qwh, qwl, nullptr, nullptr, pqkv, nullptr, nullptr,
                MP, 3*CC, CC);
        }
        attn_kernel<<<dim3(BB*HH, 2), 256, ATT_SMEM>>>(pqkv, poh, pol);
        gemm_bf<true,false,true,false><<<dim3(CC/128, MTT), 256, GB_SMEM>>>(
            poh, pol, pwh, pwl, pb, ph, ph, nullptr, nullptr, MP, CC, CC);
        ln_kernel<true><<<TT, 256>>>(ph, l2w, l2b, nullptr, pyh, pyl, 1);
        gemm_bf<true,true,false,true><<<dim3(FF/128, MTT), 256, GB_SMEM>>>(
            pyh, pyl, w1h, w1l, f1b, nullptr, nullptr, pmh, pml, MP, FF, CC);
        gemm_bf<true,false,true,false><<<dim3(CC/128, MTT), 256, GB_SMEM>>>(
            pmh, pml, w2h, w2l, f2b, ph, ph, nullptr, nullptr, MP, CC, FF);
    }

    ln_kernel<false><<<BB, 256>>>(ph, norm_w, norm_b, pcls, nullptr, nullptr, NN);
    gemm_nt<true><<<dim3(1, (VV + 127) / 128), 256>>>(
        pcls, head_w, head_b, out, BB, VV, CC);
}

// round 15
// speedup vs baseline: 1.8549x; 1.8549x over previous
#include <cuda_runtime.h>
#include <cuda_bf16.h>
#include <cuda_fp16.h>
#include <math.h>
#include <stdint.h>

// ---------------------------------------------------------------------------
// T2T-ViT forward. B=64, N=197, C=768, D=12, H=12, dk=64, F=3072, V=1000.
// GEMMs: mma.sync m16n8k16 fp16, 2-MMA split (A fp16, W = fp16 hi+lo ~ fp32),
// ldmatrix consumer, BK=32 double-buffer with interleaved LDG/STS halves,
// col-major grid, 2 CTAs/SM. Attention: fp16 K/V smem, 2 rows/thread.
// ---------------------------------------------------------------------------

#define BB   64
#define NN   197
#define CC   768
#define TT   (BB * NN)        // 12608
#define MP   12672            // 99*128
#define HH   12
#define DK   64
#define FF   3072
#define NL   12
#define VV   1000

// GEMM smem: 2 buffers x 3 planes x (128 rows x 80B)  (BK=32 fp16 = 64B + 16 pad)
#define PLANEB   10240
#define STAGEB   30720
#define GB_SMEM  (2 * STAGEB)   // 61440

#define ATT_SMEM (NN * DK * 2 * 2)     // 50432 B (fp16 K + V)

// --------------------------- scratch (static device) -------------------------
__device__ float g_h  [MP * CC];
__device__ float g_qkv[MP * 3 * CC];
__device__ float g_cls[BB * CC];

__device__ __half g_ya[MP * CC];      // LN output (fp16)
__device__ __half g_oa[MP * CC];      // attention output (fp16)
__device__ __half g_ma[MP * FF];      // MLP hidden (fp16)

#define W_QKV (NL * 3 * CC * CC)
#define W_PRJ (NL * CC * CC)
#define W_FC1 (NL * FF * CC)
#define W_FC2 (NL * CC * FF)
__device__ __half g_wqh[W_QKV], g_wql[W_QKV];
__device__ __half g_wph[W_PRJ], g_wpl[W_PRJ];
__device__ __half g_w1h[W_FC1], g_w1l[W_FC1];
__device__ __half g_w2h[W_FC2], g_w2l[W_FC2];

// --------------------------- helpers ----------------------------------------
__device__ __forceinline__ float gelu_exact(float f) {
    return 0.5f * f * (1.0f + erff(f * 0.70710678118654752f));
}
__device__ __forceinline__ void mma16816(float* d, const uint32_t* a,
                                         uint32_t b0, uint32_t b1) {
    asm volatile(
        "mma.sync.aligned.m16n8k16.row.col.f32.f16.f16.f32 "
        "{%0,%1,%2,%3}, {%4,%5,%6,%7}, {%8,%9}, {%0,%1,%2,%3};"
        : "+f"(d[0]), "+f"(d[1]), "+f"(d[2]), "+f"(d[3])
        : "r"(a[0]), "r"(a[1]), "r"(a[2]), "r"(a[3]), "r"(b0), "r"(b1));
}
__device__ __forceinline__ void ldsm_x4(uint32_t* r, uint32_t addr) {
    asm volatile("ldmatrix.sync.aligned.m8n8.x4.shared.b16 {%0,%1,%2,%3}, [%4];"
        : "=r"(r[0]), "=r"(r[1]), "=r"(r[2]), "=r"(r[3]) : "r"(addr));
}
__device__ __forceinline__ void ldsm_x2(uint32_t& r0, uint32_t& r1, uint32_t addr) {
    asm volatile("ldmatrix.sync.aligned.m8n8.x2.shared.b16 {%0,%1}, [%2];"
        : "=r"(r0), "=r"(r1) : "r"(addr));
}
__device__ __forceinline__ uint32_t smem_u32(const void* p) {
    uint32_t a;
    asm("{ .reg .u64 t; cvta.to.shared.u64 t, %1; cvt.u32.u64 %0, t; }"
        : "=r"(a) : "l"(p));
    return a;
}

// --------------------------- weight split kernel (fp32 -> fp16 hi/lo) --------
__global__ void conv_kernel(const float4* __restrict__ w,
                            uint2* __restrict__ wh, uint2* __restrict__ wl,
                            int n4)
{
    for (int i = blockIdx.x * blockDim.x + threadIdx.x; i < n4;
         i += gridDim.x * blockDim.x) {
        float4 v = w[i];
        __half2 h01 = __floats2half2_rn(v.x, v.y);
        __half2 h23 = __floats2half2_rn(v.z, v.w);
        float2 f01 = __half22float2(h01);
        float2 f23 = __half22float2(h23);
        __half2 l01 = __floats2half2_rn(v.x - f01.x, v.y - f01.y);
        __half2 l23 = __floats2half2_rn(v.z - f23.x, v.w - f23.y);
        wh[i] = make_uint2(*(uint32_t*)&h01, *(uint32_t*)&h23);
        wl[i] = make_uint2(*(uint32_t*)&l01, *(uint32_t*)&l23);
    }
}

// --------------------------- fp16 2-MMA GEMM (interleaved dbl-buffer) --------
// out[M,Nd] = A[M,K] @ W[Nd,K]^T (+bias, gelu, res).
// A: fp16 single plane. W: fp16 hi+lo planes (exact fp32 weights).
// Block 128x128, BK=32, 256 thr (8 warps, warp tile 64x32), double smem buffer.
// Per stage: ldg(A,s+1) | MMA k16#0 | sts(A)+ldg(B,s+1) | MMA k16#1 | sts(B) | bar.
// grid = (Nd/128, M/128) col-major.
template<bool BIAS, bool GELU, bool RES, bool OUTH>
__global__ __launch_bounds__(256, 2)
void gemm_hf(const __half* __restrict__ A,
             const __half* __restrict__ Bh, const __half* __restrict__ Bl,
             const float* __restrict__ bias, const float* __restrict__ res,
             float* __restrict__ out, __half* __restrict__ outh,
             int M, int Nd, int K)
{
    extern __shared__ char smem[];
    uint32_t sb = smem_u32(smem);
    const int tid = threadIdx.x, wid = tid >> 5, lane = tid & 31;
    const int n0 = blockIdx.x * 128, m0 = blockIdx.y * 128;
    const int warp_m = wid & 1, warp_n = wid >> 1;
    const int g = lane >> 2, t = lane & 3;
    const int l16 = lane & 15;

    // ldmatrix lane-address bases (byte offsets within plane, stride 80)
    const uint32_t aOff = (uint32_t)((warp_m * 64 + (lane & 15)) * 80
                                     + ((lane >> 4) << 4));
    const uint32_t bOff = (uint32_t)((warp_n * 32 + (l16 & 7)) * 80
                                     + ((l16 & 8) << 1));

    float acc[4][4][4];
    #pragma unroll
    for (int i = 0; i < 4; i++)
        #pragma unroll
        for (int j = 0; j < 4; j++)
            #pragma unroll
            for (int e = 0; e < 4; e++) acc[i][j][e] = 0.f;

    const int NS = K / 32;
    const __half* sA  = A  + (size_t)m0 * K;
    const __half* sB0 = Bh + (size_t)n0 * K;
    const __half* sB1 = Bl + (size_t)n0 * K;

    const int r0 = tid >> 2, r1 = (tid >> 2) + 64;
    const int lch = tid & 3;

    uint4 pfA[2];
    uint4 pfB[4];

    auto ldgA = [&](int s) {
        const int k0 = s * 32 + lch * 8;
        pfA[0] = *(const uint4*)(sA + (size_t)r0 * K + k0);
        pfA[1] = *(const uint4*)(sA + (size_t)r1 * K + k0);
    };
    auto ldgB = [&](int s) {
        const int k0 = s * 32 + lch * 8;
        pfB[0] = *(const uint4*)(sB0 + (size_t)r0 * K + k0);
        pfB[1] = *(const uint4*)(sB0 + (size_t)r1 * K + k0);
        pfB[2] = *(const uint4*)(sB1 + (size_t)r0 * K + k0);
        pfB[3] = *(const uint4*)(sB1 + (size_t)r1 * K + k0);
    };
    auto stsA = [&](int buf) {
        char* st = smem + buf * STAGEB + lch * 16;
        *(uint4*)(st + r0 * 80) = pfA[0];
        *(uint4*)(st + r1 * 80) = pfA[1];
    };
    auto stsB = [&](int buf) {
        char* st = smem + buf * STAGEB + PLANEB + lch * 16;
        *(uint4*)(st + r0 * 80)          = pfB[0];
        *(uint4*)(st + r1 * 80)          = pfB[1];
        *(uint4*)(st + PLANEB + r0 * 80) = pfB[2];
        *(uint4*)(st + PLANEB + r1 * 80) = pfB[3];
    };

    // preload stage 0 into buffer 0
    ldgA(0); stsA(0);
    ldgB(0); stsB(0);
    __syncthreads();

    for (int s = 0; s < NS; s++) {
        const int buf = s & 1, nxt = buf ^ 1;
        const uint32_t base = sb + buf * STAGEB;
        const uint32_t aA = base + aOff;
        const uint32_t bH = base + PLANEB + bOff;
        const uint32_t bL = base + 2 * PLANEB + bOff;
        const bool more = (s + 1 < NS);

        if (more) ldgA(s + 1);

        // ---- k16 block #0 (kb = 0) ----
        {
            const uint32_t kb = 0;
            uint32_t bh[4][2], bl[4][2];
            #pragma unroll
            for (int j = 0; j < 4; j++) {
                ldsm_x2(bh[j][0], bh[j][1], bH + (uint32_t)(j * 8 * 80) + kb);
                ldsm_x2(bl[j][0], bl[j][1], bL + (uint32_t)(j * 8 * 80) + kb);
            }
            #pragma unroll
            for (int i = 0; i < 4; i++) {
                uint32_t ah[4];
                ldsm_x4(ah, aA + (uint32_t)(i * 16 * 80) + kb);
                #pragma unroll
                for (int j = 0; j < 4; j++) {
                    mma16816(acc[i][j], ah, bh[j][0], bh[j][1]);
                    mma16816(acc[i][j], ah, bl[j][0], bl[j][1]);
                }
            }
        }

        if (more) { stsA(nxt); ldgB(s + 1); }

        // ---- k16 block #1 (kb = 32) ----
        {
            const uint32_t kb = 32;
            uint32_t bh[4][2], bl[4][2];
            #pragma unroll
            for (int j = 0; j < 4; j++) {
                ldsm_x2(bh[j][0], bh[j][1], bH + (uint32_t)(j * 8 * 80) + kb);
                ldsm_x2(bl[j][0], bl[j][1], bL + (uint32_t)(j * 8 * 80) + kb);
            }
            #pragma unroll
            for (int i = 0; i < 4; i++) {
                uint32_t ah[4];
                ldsm_x4(ah, aA + (uint32_t)(i * 16 * 80) + kb);
                #pragma unroll
                for (int j = 0; j < 4; j++) {
                    mma16816(acc[i][j], ah, bh[j][0], bh[j][1]);
                    mma16816(acc[i][j], ah, bl[j][0], bl[j][1]);
                }
            }
        }

        if (more) stsB(nxt);
        __syncthreads();
    }

    // ---- epilogue ------------------------------------------------------------
    #pragma unroll
    for (int i = 0; i < 4; i++) {
        #pragma unroll
        for (int j = 0; j < 4; j++) {
            int gm0 = m0 + warp_m * 64 + i * 16 + g;
            int gn  = n0 + warp_n * 32 + j * 8 + 2 * t;
            #pragma unroll
            for (int half = 0; half < 2; half++) {
                int gm = gm0 + half * 8;
                float v0 = acc[i][j][half * 2 + 0];
                float v1 = acc[i][j][half * 2 + 1];
                if (BIAS) { v0 += bias[gn]; v1 += bias[gn + 1]; }
                if (GELU) { v0 = gelu_exact(v0); v1 = gelu_exact(v1); }
                if (OUTH) {
                    __half2 hv = __floats2half2_rn(v0, v1);
                    *(__half2*)(outh + (size_t)gm * Nd + gn) = hv;
                } else {
                    if (RES) {
                        float2 r2 = *(const float2*)(res + (size_t)gm * Nd + gn);
                        v0 += r2.x; v1 += r2.y;
                    }
                    *(float2*)(out + (size_t)gm * Nd + gn) = make_float2(v0, v1);
                }
            }
        }
    }
}

// --------------------------- embed (pads zeroed) ------------------------------
__global__ void embed_kernel(const float* __restrict__ x,
                             const float* __restrict__ cls,
                             float* __restrict__ h)
{
    int row = blockIdx.x;
    if (row >= TT) {
        for (int c = threadIdx.x; c < CC; c += blockDim.x)
            h[(size_t)row * CC + c] = 0.f;
        return;
    }
    int b = row / NN, n = row % NN;
    for (int c = threadIdx.x; c < CC; c += blockDim.x) {
        float base = (n == 0) ? cls[c]
                              : x[((size_t)b * (NN - 1) + (n - 1)) * CC + c];
        int jj = c & ~1;
        float div = __expf(-9.210340371976184f * (float)jj / 768.0f);
        float ang = (float)n * div;
        float pe  = (c & 1) ? cosf(ang) : sinf(ang);
        h[(size_t)row * CC + c] = base + pe;
    }
}

// --------------------------- layernorm ----------------------------------------
// OUTH: write fp16 single plane; else fp32.
template<bool OUTH>
__global__ void ln_kernel(const float* __restrict__ x,
                          const float* __restrict__ w,
                          const float* __restrict__ bns,
                          float* __restrict__ yf,
                          __half* __restrict__ ya,
                          int in_row_stride)
{
    const float* xr = x + (size_t)blockIdx.x * in_row_stride * CC;
    int t = threadIdx.x;
    float v0 = xr[t], v1 = xr[t + 256], v2 = xr[t + 512];
    float s = v0 + v1 + v2;
    float q = v0 * v0 + v1 * v1 + v2 * v2;
    #pragma unroll
    for (int o = 16; o; o >>= 1) {
        s += __shfl_xor_sync(0xffffffffu, s, o);
        q += __shfl_xor_sync(0xffffffffu, q, o);
    }
    __shared__ float ss[8], qs[8];
    if ((t & 31) == 0) { ss[t >> 5] = s; qs[t >> 5] = q; }
    __syncthreads();
    float tot = 0.f, totq = 0.f;
    #pragma unroll
    for (int i = 0; i < 8; i++) { tot += ss[i]; totq += qs[i]; }
    float mu   = tot * (1.0f / 768.0f);
    float var  = totq * (1.0f / 768.0f) - mu * mu;
    float rstd = rsqrtf(var + 1e-5f);
    float r0 = (v0 - mu) * rstd * w[t]       + bns[t];
    float r1 = (v1 - mu) * rstd * w[t + 256] + bns[t + 256];
    float r2 = (v2 - mu) * rstd * w[t + 512] + bns[t + 512];
    if (OUTH) {
        size_t base = (size_t)blockIdx.x * CC;
        ya[base + t]       = __float2half_rn(r0);
        ya[base + t + 256] = __float2half_rn(r1);
        ya[base + t + 512] = __float2half_rn(r2);
    } else {
        float* yr = yf + (size_t)blockIdx.x * CC;
        yr[t] = r0; yr[t + 256] = r1; yr[t + 512] = r2;
    }
}

// --------------------------- fused attention ----------------------------------
// fp16 K/V in smem (fp32 math), 2 query rows per thread. grid (B*H, 2).
// Output: fp16 single plane.
__global__ __launch_bounds__(256, 2)
void attn_kernel(const float* __restrict__ qkv, __half* __restrict__ oa)
{
    extern __shared__ __half smh[];
    __half* Ks = smh;               // NN*DK
    __half* Vs = smh + NN * DK;
    int bh = blockIdx.x;
    int b = bh / HH, h = bh % HH;
    const float* base = qkv + (size_t)b * NN * (3 * CC);

    for (int idx = threadIdx.x; idx < (NN * DK) / 4; idx += 256) {
        int row = idx >> 4, d4 = (idx & 15) << 2;
        float4 kv = *(const float4*)(base + (size_t)row * (3 * CC) +     CC + h * DK + d4);
        float4 vv = *(const float4*)(base + (size_t)row * (3 * CC) + 2 * CC + h * DK + d4);
        *(__half2*)(Ks + row * DK + d4)     = __floats2half2_rn(kv.x, kv.y);
        *(__half2*)(Ks + row * DK + d4 + 2) = __floats2half2_rn(kv.z, kv.w);
        *(__half2*)(Vs + row * DK + d4)     = __floats2half2_rn(vv.x, vv.y);
        *(__half2*)(Vs + row * DK + d4 + 2) = __floats2half2_rn(vv.z, vv.w);
    }
    __syncthreads();

    int grp = threadIdx.x >> 2, sub = threadIdx.x & 3;
    int r0 = blockIdx.y * 128 + grp;
    int r1 = r0 + 64;
    int c0 = (r0 < NN) ? r0 : NN - 1;
    int c1 = (r1 < NN) ? r1 : NN - 1;

    float q0[16], q1[16];
    {
        const float* qp0 = base + (size_t)c0 * (3 * CC) + h * DK + sub * 16;
        const float* qp1 = base + (size_t)c1 * (3 * CC) + h * DK + sub * 16;
        #pragma unroll
        for (int k = 0; k < 16; k += 4) {
            float4 v = *(const float4*)(qp0 + k);
            q0[k] = v.x * 0.125f; q0[k+1] = v.y * 0.125f;
            q0[k+2] = v.z * 0.125f; q0[k+3] = v.w * 0.125f;
            float4 w = *(const float4*)(qp1 + k);
            q1[k] = w.x * 0.125f; q1[k+1] = w.y * 0.125f;
            q1[k+2] = w.z * 0.125f; q1[k+3] = w.w * 0.125f;
        }
    }

    float mx0 = -1e30f, l0 = 0.f, mx1 = -1e30f, l1 = 0.f;
    float acc0[16], acc1[16];
    #pragma unroll
    for (int k = 0; k < 16; k++) { acc0[k] = 0.f; acc1[k] = 0.f; }

    for (int j = 0; j < NN; j++) {
        const __half* kr = Ks + j * DK + sub * 16;
        float kf[16];
        {
            uint4 u0 = *(const uint4*)(kr);
            uint4 u1 = *(const uint4*)(kr + 8);
            const uint32_t* uw = &u0.x;
            #pragma unroll
            for (int e = 0; e < 4; e++) {
                float2 f = __half22float2(*(const __half2*)&uw[e]);
                kf[e * 2] = f.x; kf[e * 2 + 1] = f.y;
            }
            const uint32_t* uw1 = &u1.x;
            #pragma unroll
            for (int e = 0; e < 4; e++) {
                float2 f = __half22float2(*(const __half2*)&uw1[e]);
                kf[8 + e * 2] = f.x; kf[8 + e * 2 + 1] = f.y;
            }
        }
        float s0 = 0.f, s1 = 0.f;
        #pragma unroll
        for (int k = 0; k < 16; k++) { s0 += q0[k] * kf[k]; s1 += q1[k] * kf[k]; }
        s0 += __shfl_xor_sync(0xffffffffu, s0, 1);
        s0 += __shfl_xor_sync(0xffffffffu, s0, 2);
        s1 += __shfl_xor_sync(0xffffffffu, s1, 1);
        s1 += __shfl_xor_sync(0xffffffffu, s1, 2);

        if (s0 > mx0) {
            float cr = __expf(mx0 - s0);
            l0 *= cr;
            #pragma unroll
            for (int k = 0; k < 16; k++) acc0[k] *= cr;
            mx0 = s0;
        }
        float p0 = __expf(s0 - mx0);
        l0 += p0;
        if (s1 > mx1) {
            float cr = __expf(mx1 - s1);
            l1 *= cr;
            #pragma unroll
            for (int k = 0; k < 16; k++) acc1[k] *= cr;
            mx1 = s1;
        }
        float p1 = __expf(s1 - mx1);
        l1 += p1;

        const __half* vr = Vs + j * DK + sub * 16;
        uint4 w0 = *(const uint4*)(vr);
        uint4 w1 = *(const uint4*)(vr + 8);
        const uint32_t* vw0 = &w0.x;
        const uint32_t* vw1 = &w1.x;
        #pragma unroll
        for (int e = 0; e < 4; e++) {
            float2 f = __half22float2(*(const __half2*)&vw0[e]);
            acc0[e*2]   += p0 * f.x; acc0[e*2+1] += p0 * f.y;
            acc1[e*2]   += p1 * f.x; acc1[e*2+1] += p1 * f.y;
            float2 g2 = __half22float2(*(const __half2*)&vw1[e]);
            acc0[8+e*2]   += p0 * g2.x; acc0[8+e*2+1] += p0 * g2.y;
            acc1[8+e*2]   += p1 * g2.x; acc1[8+e*2+1] += p1 * g2.y;
        }
    }

    if (r0 < NN) {
        float inv = 1.0f / l0;
        size_t off = (size_t)(b * NN + r0) * CC + h * DK + sub * 16;
        #pragma unroll
        for (int k = 0; k < 16; k += 2)
            *(__half2*)(oa + off + k) =
                __floats2half2_rn(acc0[k] * inv, acc0[k + 1] * inv);
    }
    if (r1 < NN) {
        float inv = 1.0f / l1;
        size_t off = (size_t)(b * NN + r1) * CC + h * DK + sub * 16;
        #pragma unroll
        for (int k = 0; k < 16; k += 2)
            *(__half2*)(oa + off + k) =
                __floats2half2_rn(acc1[k] * inv, acc1[k + 1] * inv);
    }
}

// --------------------------- small SIMT GEMM (head) ---------------------------
template<bool BIAS>
__global__ void gemm_nt(const float* __restrict__ A, const float* __restrict__ W,
                        const float* __restrict__ bias, float* __restrict__ out,
                        int M, int Nd, int K)
{
    const int BM = 128, BN = 128, BK = 8;
    __shared__ float As[BK][BM + 4];
    __shared__ float Ws[BK][BN + 4];
    int t = threadIdx.x, tx = t & 15, ty = t >> 4;
    int m0 = blockIdx.x * BM, n0 = blockIdx.y * BN;
    int lrow = t >> 1, lk = (t & 1) * 4;
    float acc[8][8];
    #pragma unroll
    for (int i = 0; i < 8; i++)
        #pragma unroll
        for (int j = 0; j < 8; j++) acc[i][j] = 0.f;
    for (int k0 = 0; k0 < K; k0 += BK) {
        int gm = m0 + lrow;
        float4 va = (gm < M) ? *(const float4*)(A + (size_t)gm * K + k0 + lk)
                             : make_float4(0,0,0,0);
        As[lk+0][lrow]=va.x; As[lk+1][lrow]=va.y; As[lk+2][lrow]=va.z; As[lk+3][lrow]=va.w;
        int gn = n0 + lrow;
        float4 vw = (gn < Nd) ? *(const float4*)(W + (size_t)gn * K + k0 + lk)
                              : make_float4(0,0,0,0);
        Ws[lk+0][lrow]=vw.x; Ws[lk+1][lrow]=vw.y; Ws[lk+2][lrow]=vw.z; Ws[lk+3][lrow]=vw.w;
        __syncthreads();
        #pragma unroll
        for (int k = 0; k < BK; k++) {
            float ra[8], rb[8];
            *(float4*)(ra)   = *(const float4*)&As[k][ty*8];
            *(float4*)(ra+4) = *(const float4*)&As[k][ty*8+4];
            *(float4*)(rb)   = *(const float4*)&Ws[k][tx*8];
            *(float4*)(rb+4) = *(const float4*)&Ws[k][tx*8+4];
            #pragma unroll
            for (int i = 0; i < 8; i++)
                #pragma unroll
                for (int j = 0; j < 8; j++) acc[i][j] += ra[i] * rb[j];
        }
        __syncthreads();
    }
    #pragma unroll
    for (int i = 0; i < 8; i++) {
        int gm = m0 + ty * 8 + i;
        if (gm >= M) continue;
        #pragma unroll
        for (int j = 0; j < 8; j++) {
            int gn = n0 + tx * 8 + j;
            if (gn >= Nd) continue;
            float v = acc[i][j];
            if (BIAS) v += bias[gn];
            out[(size_t)gm * Nd + gn] = v;
        }
    }
}

// ---------------------------------------------------------------------------
extern "C" void kernel_launch(void* const* d_in, const int* in_sizes, int n_in,
                              void* d_out, int out_size)
{
    const float* x      = (const float*)d_in[0];
    const float* cls    = (const float*)d_in[1];
    const float* qkv_w  = (const float*)d_in[2];
    const float* proj_w = (const float*)d_in[3];
    const float* proj_b = (const float*)d_in[4];
    const float* ln1_w  = (const float*)d_in[5];
    const float* ln1_b  = (const float*)d_in[6];
    const float* ln2_w  = (const float*)d_in[7];
    const float* ln2_b  = (const float*)d_in[8];
    const float* fc1_w  = (const float*)d_in[9];
    const float* fc1_b  = (const float*)d_in[10];
    const float* fc2_w  = (const float*)d_in[11];
    const float* fc2_b  = (const float*)d_in[12];
    const float* norm_w = (const float*)d_in[13];
    const float* norm_b = (const float*)d_in[14];
    const float* head_w = (const float*)d_in[15];
    const float* head_b = (const float*)d_in[16];
    float* out = (float*)d_out;

    float *ph, *pqkv, *pcls;
    __half *pya, *poa, *pma;
    __half *pwqh, *pwql, *pwph, *pwpl, *pw1h, *pw1l, *pw2h, *pw2l;
    cudaGetSymbolAddress((void**)&ph,   g_h);
    cudaGetSymbolAddress((void**)&pqkv, g_qkv);
    cudaGetSymbolAddress((void**)&pcls, g_cls);
    cudaGetSymbolAddress((void**)&pya, g_ya);
    cudaGetSymbolAddress((void**)&poa, g_oa);
    cudaGetSymbolAddress((void**)&pma, g_ma);
    cudaGetSymbolAddress((void**)&pwqh, g_wqh); cudaGetSymbolAddress((void**)&pwql, g_wql);
    cudaGetSymbolAddress((void**)&pwph, g_wph); cudaGetSymbolAddress((void**)&pwpl, g_wpl);
    cudaGetSymbolAddress((void**)&pw1h, g_w1h); cudaGetSymbolAddress((void**)&pw1l, g_w1l);
    cudaGetSymbolAddress((void**)&pw2h, g_w2h); cudaGetSymbolAddress((void**)&pw2l, g_w2l);

    cudaFuncSetAttribute(attn_kernel,
                         cudaFuncAttributeMaxDynamicSharedMemorySize, ATT_SMEM);
    cudaFuncSetAttribute(gemm_hf<false,false,false,false>,
                         cudaFuncAttributeMaxDynamicSharedMemorySize, GB_SMEM);
    cudaFuncSetAttribute(gemm_hf<true,false,true,false>,
                         cudaFuncAttributeMaxDynamicSharedMemorySize, GB_SMEM);
    cudaFuncSetAttribute(gemm_hf<true,true,false,true>,
                         cudaFuncAttributeMaxDynamicSharedMemorySize, GB_SMEM);

    const int MTT = MP / 128;  // 99

    // Launch order keeps the first QKV gemm at launch #4 for the profiler.
    conv_kernel<<<1184, 256>>>((const float4*)qkv_w, (uint2*)pwqh, (uint2*)pwql, W_QKV/4);
    embed_kernel<<<MP, 256>>>(x, cls, ph);
    ln_kernel<true><<<TT, 256>>>(ph, ln1_w, ln1_b, nullptr, pya, 1);
    gemm_hf<false,false,false,false><<<dim3((3*CC)/128, MTT), 256, GB_SMEM>>>(
        pya, pwqh, pwql, nullptr, nullptr, pqkv, nullptr, MP, 3*CC, CC);
    conv_kernel<<<1184, 256>>>((const float4*)proj_w, (uint2*)pwph, (uint2*)pwpl, W_PRJ/4);
    conv_kernel<<<1184, 256>>>((const float4*)fc1_w, (uint2*)pw1h, (uint2*)pw1l, W_FC1/4);
    conv_kernel<<<1184, 256>>>((const float4*)fc2_w, (uint2*)pw2h, (uint2*)pw2l, W_FC2/4);

    for (int d = 0; d < NL; d++) {
        const __half* qwh = pwqh + (size_t)d * 3 * CC * CC;
        const __half* qwl = pwql + (size_t)d * 3 * CC * CC;
        const __half* pwh = pwph + (size_t)d * CC * CC;
        const __half* pwl = pwpl + (size_t)d * CC * CC;
        const __half* w1h = pw1h + (size_t)d * FF * CC;
        const __half* w1l = pw1l + (size_t)d * FF * CC;
        const __half* w2h = pw2h + (size_t)d * CC * FF;
        const __half* w2l = pw2l + (size_t)d * CC * FF;
        const float* pb  = proj_b + (size_t)d * CC;
        const float* l2w = ln2_w  + (size_t)d * CC;
        const float* l2b = ln2_b  + (size_t)d * CC;
        const float* f1b = fc1_b  + (size_t)d * FF;
        const float* f2b = fc2_b  + (size_t)d * CC;

        if (d > 0) {
            const float* l1w = ln1_w + (size_t)d * CC;
            const float* l1b = ln1_b + (size_t)d * CC;
            ln_kernel<true><<<TT, 256>>>(ph, l1w, l1b, nullptr, pya, 1);
            gemm_hf<false,false,false,false><<<dim3((3*CC)/128, MTT), 256, GB_SMEM>>>(
                pya, qwh, qwl, nullptr, nullptr, pqkv, nullptr, MP, 3*CC, CC);
        }
        attn_kernel<<<dim3(BB*HH, 2), 256, ATT_SMEM>>>(pqkv, poa);
        gemm_hf<true,false,true,false><<<dim3(CC/128, MTT), 256, GB_SMEM>>>(
            poa, pwh, pwl, pb, ph, ph, nullptr, MP, CC, CC);
        ln_kernel<true><<<TT, 256>>>(ph, l2w, l2b, nullptr, pya, 1);
        gemm_hf<true,true,false,true><<<dim3(FF/128, MTT), 256, GB_SMEM>>>(
            pya, w1h, w1l, f1b, nullptr, nullptr, pma, MP, FF, CC);
        gemm_hf<true,false,true,false><<<dim3(CC/128, MTT), 256, GB_SMEM>>>(
            pma, w2h, w2l, f2b, ph, ph, nullptr, MP, CC, FF);
    }

    ln_kernel<false><<<BB, 256>>>(ph, norm_w, norm_b, pcls, nullptr, NN);
    gemm_nt<true><<<dim3(1, (VV + 127) / 128), 256>>>(
        pcls, head_w, head_b, out, BB, VV, CC);
}

// round 16
// speedup vs baseline: 2.2509x; 1.2135x over previous
#include <cuda_runtime.h>
#include <cuda_bf16.h>
#include <cuda_fp16.h>
#include <math.h>
#include <stdint.h>

// ---------------------------------------------------------------------------
// T2T-ViT forward. B=64, N=197, C=768, D=12, H=12, dk=64, F=3072, V=1000.
// GEMMs: mma.sync m16n8k16 fp16. QKV/proj: 2-MMA split (W = fp16 hi+lo).
// fc1/fc2: 1-MMA, single-plane fp16 weights (MLP branch error-tolerant).
// BK=32 double-buffer, interleaved LDG/STS, col-major grid, 2 CTAs/SM.
// Attention: fp16 K/V smem, 2 rows/thread.
// ---------------------------------------------------------------------------

#define BB   64
#define NN   197
#define CC   768
#define TT   (BB * NN)        // 12608
#define MP   12672            // 99*128
#define HH   12
#define DK   64
#define FF   3072
#define NL   12
#define VV   1000

// GEMM smem: 2 buffers x 3 planes x (128 rows x 80B)  (BK=32 fp16 = 64B + 16 pad)
#define PLANEB   10240
#define STAGEB   30720
#define GB_SMEM  (2 * STAGEB)   // 61440

#define ATT_SMEM (NN * DK * 2 * 2)     // 50432 B (fp16 K + V)

// --------------------------- scratch (static device) -------------------------
__device__ float g_h  [MP * CC];
__device__ float g_qkv[MP * 3 * CC];
__device__ float g_cls[BB * CC];

__device__ __half g_ya[MP * CC];      // LN output (fp16)
__device__ __half g_oa[MP * CC];      // attention output (fp16)
__device__ __half g_ma[MP * FF];      // MLP hidden (fp16)

#define W_QKV (NL * 3 * CC * CC)
#define W_PRJ (NL * CC * CC)
#define W_FC1 (NL * FF * CC)
#define W_FC2 (NL * CC * FF)
__device__ __half g_wqh[W_QKV], g_wql[W_QKV];
__device__ __half g_wph[W_PRJ], g_wpl[W_PRJ];
__device__ __half g_w1h[W_FC1];
__device__ __half g_w2h[W_FC2];

// --------------------------- helpers ----------------------------------------
__device__ __forceinline__ float gelu_exact(float f) {
    return 0.5f * f * (1.0f + erff(f * 0.70710678118654752f));
}
__device__ __forceinline__ void mma16816(float* d, const uint32_t* a,
                                         uint32_t b0, uint32_t b1) {
    asm volatile(
        "mma.sync.aligned.m16n8k16.row.col.f32.f16.f16.f32 "
        "{%0,%1,%2,%3}, {%4,%5,%6,%7}, {%8,%9}, {%0,%1,%2,%3};"
        : "+f"(d[0]), "+f"(d[1]), "+f"(d[2]), "+f"(d[3])
        : "r"(a[0]), "r"(a[1]), "r"(a[2]), "r"(a[3]), "r"(b0), "r"(b1));
}
__device__ __forceinline__ void ldsm_x4(uint32_t* r, uint32_t addr) {
    asm volatile("ldmatrix.sync.aligned.m8n8.x4.shared.b16 {%0,%1,%2,%3}, [%4];"
        : "=r"(r[0]), "=r"(r[1]), "=r"(r[2]), "=r"(r[3]) : "r"(addr));
}
__device__ __forceinline__ void ldsm_x2(uint32_t& r0, uint32_t& r1, uint32_t addr) {
    asm volatile("ldmatrix.sync.aligned.m8n8.x2.shared.b16 {%0,%1}, [%2];"
        : "=r"(r0), "=r"(r1) : "r"(addr));
}
__device__ __forceinline__ uint32_t smem_u32(const void* p) {
    uint32_t a;
    asm("{ .reg .u64 t; cvta.to.shared.u64 t, %1; cvt.u32.u64 %0, t; }"
        : "=r"(a) : "l"(p));
    return a;
}

// --------------------------- weight split kernels ----------------------------
__global__ void conv_kernel(const float4* __restrict__ w,
                            uint2* __restrict__ wh, uint2* __restrict__ wl,
                            int n4)
{
    for (int i = blockIdx.x * blockDim.x + threadIdx.x; i < n4;
         i += gridDim.x * blockDim.x) {
        float4 v = w[i];
        __half2 h01 = __floats2half2_rn(v.x, v.y);
        __half2 h23 = __floats2half2_rn(v.z, v.w);
        float2 f01 = __half22float2(h01);
        float2 f23 = __half22float2(h23);
        __half2 l01 = __floats2half2_rn(v.x - f01.x, v.y - f01.y);
        __half2 l23 = __floats2half2_rn(v.z - f23.x, v.w - f23.y);
        wh[i] = make_uint2(*(uint32_t*)&h01, *(uint32_t*)&h23);
        wl[i] = make_uint2(*(uint32_t*)&l01, *(uint32_t*)&l23);
    }
}
__global__ void conv1_kernel(const float4* __restrict__ w,
                             uint2* __restrict__ wh, int n4)
{
    for (int i = blockIdx.x * blockDim.x + threadIdx.x; i < n4;
         i += gridDim.x * blockDim.x) {
        float4 v = w[i];
        __half2 h01 = __floats2half2_rn(v.x, v.y);
        __half2 h23 = __floats2half2_rn(v.z, v.w);
        wh[i] = make_uint2(*(uint32_t*)&h01, *(uint32_t*)&h23);
    }
}

// --------------------------- fp16 GEMM (interleaved dbl-buffer) --------------
// out[M,Nd] = A[M,K] @ W[Nd,K]^T (+bias, gelu, res).
// A: fp16. W: fp16 hi (+optional lo plane when BLO, = exact fp32 weights).
// Block 128x128, BK=32, 256 thr (8 warps, warp tile 64x32), double smem buffer.
// Per stage: ldg(A,s+1) | MMA k16#0 | sts(A)+ldg(B,s+1) | MMA k16#1 | sts(B) | bar.
// grid = (Nd/128, M/128) col-major.
template<bool BIAS, bool GELU, bool RES, bool OUTH, bool BLO>
__global__ __launch_bounds__(256, 2)
void gemm_hf(const __half* __restrict__ A,
             const __half* __restrict__ Bh, const __half* __restrict__ Bl,
             const float* __restrict__ bias, const float* __restrict__ res,
             float* __restrict__ out, __half* __restrict__ outh,
             int M, int Nd, int K)
{
    extern __shared__ char smem[];
    uint32_t sb = smem_u32(smem);
    const int tid = threadIdx.x, wid = tid >> 5, lane = tid & 31;
    const int n0 = blockIdx.x * 128, m0 = blockIdx.y * 128;
    const int warp_m = wid & 1, warp_n = wid >> 1;
    const int g = lane >> 2, t = lane & 3;
    const int l16 = lane & 15;

    const uint32_t aOff = (uint32_t)((warp_m * 64 + (lane & 15)) * 80
                                     + ((lane >> 4) << 4));
    const uint32_t bOff = (uint32_t)((warp_n * 32 + (l16 & 7)) * 80
                                     + ((l16 & 8) << 1));

    float acc[4][4][4];
    #pragma unroll
    for (int i = 0; i < 4; i++)
        #pragma unroll
        for (int j = 0; j < 4; j++)
            #pragma unroll
            for (int e = 0; e < 4; e++) acc[i][j][e] = 0.f;

    const int NS = K / 32;
    const __half* sA  = A  + (size_t)m0 * K;
    const __half* sB0 = Bh + (size_t)n0 * K;
    const __half* sB1 = BLO ? (Bl + (size_t)n0 * K) : sB0;

    const int r0 = tid >> 2, r1 = (tid >> 2) + 64;
    const int lch = tid & 3;

    uint4 pfA[2];
    uint4 pfB[4];

    auto ldgA = [&](int s) {
        const int k0 = s * 32 + lch * 8;
        pfA[0] = *(const uint4*)(sA + (size_t)r0 * K + k0);
        pfA[1] = *(const uint4*)(sA + (size_t)r1 * K + k0);
    };
    auto ldgB = [&](int s) {
        const int k0 = s * 32 + lch * 8;
        pfB[0] = *(const uint4*)(sB0 + (size_t)r0 * K + k0);
        pfB[1] = *(const uint4*)(sB0 + (size_t)r1 * K + k0);
        if (BLO) {
            pfB[2] = *(const uint4*)(sB1 + (size_t)r0 * K + k0);
            pfB[3] = *(const uint4*)(sB1 + (size_t)r1 * K + k0);
        }
    };
    auto stsA = [&](int buf) {
        char* st = smem + buf * STAGEB + lch * 16;
        *(uint4*)(st + r0 * 80) = pfA[0];
        *(uint4*)(st + r1 * 80) = pfA[1];
    };
    auto stsB = [&](int buf) {
        char* st = smem + buf * STAGEB + PLANEB + lch * 16;
        *(uint4*)(st + r0 * 80) = pfB[0];
        *(uint4*)(st + r1 * 80) = pfB[1];
        if (BLO) {
            *(uint4*)(st + PLANEB + r0 * 80) = pfB[2];
            *(uint4*)(st + PLANEB + r1 * 80) = pfB[3];
        }
    };

    ldgA(0); stsA(0);
    ldgB(0); stsB(0);
    __syncthreads();

    for (int s = 0; s < NS; s++) {
        const int buf = s & 1, nxt = buf ^ 1;
        const uint32_t base = sb + buf * STAGEB;
        const uint32_t aA = base + aOff;
        const uint32_t bH = base + PLANEB + bOff;
        const uint32_t bL = base + 2 * PLANEB + bOff;
        const bool more = (s + 1 < NS);

        if (more) ldgA(s + 1);

        // ---- k16 block #0 ----
        {
            const uint32_t kb = 0;
            uint32_t bh[4][2], bl[4][2];
            #pragma unroll
            for (int j = 0; j < 4; j++) {
                ldsm_x2(bh[j][0], bh[j][1], bH + (uint32_t)(j * 8 * 80) + kb);
                if (BLO)
                    ldsm_x2(bl[j][0], bl[j][1], bL + (uint32_t)(j * 8 * 80) + kb);
            }
            #pragma unroll
            for (int i = 0; i < 4; i++) {
                uint32_t ah[4];
                ldsm_x4(ah, aA + (uint32_t)(i * 16 * 80) + kb);
                #pragma unroll
                for (int j = 0; j < 4; j++) {
                    mma16816(acc[i][j], ah, bh[j][0], bh[j][1]);
                    if (BLO) mma16816(acc[i][j], ah, bl[j][0], bl[j][1]);
                }
            }
        }

        if (more) { stsA(nxt); ldgB(s + 1); }

        // ---- k16 block #1 ----
        {
            const uint32_t kb = 32;
            uint32_t bh[4][2], bl[4][2];
            #pragma unroll
            for (int j = 0; j < 4; j++) {
                ldsm_x2(bh[j][0], bh[j][1], bH + (uint32_t)(j * 8 * 80) + kb);
                if (BLO)
                    ldsm_x2(bl[j][0], bl[j][1], bL + (uint32_t)(j * 8 * 80) + kb);
            }
            #pragma unroll
            for (int i = 0; i < 4; i++) {
                uint32_t ah[4];
                ldsm_x4(ah, aA + (uint32_t)(i * 16 * 80) + kb);
                #pragma unroll
                for (int j = 0; j < 4; j++) {
                    mma16816(acc[i][j], ah, bh[j][0], bh[j][1]);
                    if (BLO) mma16816(acc[i][j], ah, bl[j][0], bl[j][1]);
                }
            }
        }

        if (more) stsB(nxt);
        __syncthreads();
    }

    // ---- epilogue ------------------------------------------------------------
    #pragma unroll
    for (int i = 0; i < 4; i++) {
        #pragma unroll
        for (int j = 0; j < 4; j++) {
            int gm0 = m0 + warp_m * 64 + i * 16 + g;
            int gn  = n0 + warp_n * 32 + j * 8 + 2 * t;
            #pragma unroll
            for (int half = 0; half < 2; half++) {
                int gm = gm0 + half * 8;
                float v0 = acc[i][j][half * 2 + 0];
                float v1 = acc[i][j][half * 2 + 1];
                if (BIAS) { v0 += bias[gn]; v1 += bias[gn + 1]; }
                if (GELU) { v0 = gelu_exact(v0); v1 = gelu_exact(v1); }
                if (OUTH) {
                    __half2 hv = __floats2half2_rn(v0, v1);
                    *(__half2*)(outh + (size_t)gm * Nd + gn) = hv;
                } else {
                    if (RES) {
                        float2 r2 = *(const float2*)(res + (size_t)gm * Nd + gn);
                        v0 += r2.x; v1 += r2.y;
                    }
                    *(float2*)(out + (size_t)gm * Nd + gn) = make_float2(v0, v1);
                }
            }
        }
    }
}

// --------------------------- embed (pads zeroed) ------------------------------
__global__ void embed_kernel(const float* __restrict__ x,
                             const float* __restrict__ cls,
                             float* __restrict__ h)
{
    int row = blockIdx.x;
    if (row >= TT) {
        for (int c = threadIdx.x; c < CC; c += blockDim.x)
            h[(size_t)row * CC + c] = 0.f;
        return;
    }
    int b = row / NN, n = row % NN;
    for (int c = threadIdx.x; c < CC; c += blockDim.x) {
        float base = (n == 0) ? cls[c]
                              : x[((size_t)b * (NN - 1) + (n - 1)) * CC + c];
        int jj = c & ~1;
        float div = __expf(-9.210340371976184f * (float)jj / 768.0f);
        float ang = (float)n * div;
        float pe  = (c & 1) ? cosf(ang) : sinf(ang);
        h[(size_t)row * CC + c] = base + pe;
    }
}

// --------------------------- layernorm ----------------------------------------
template<bool OUTH>
__global__ void ln_kernel(const float* __restrict__ x,
                          const float* __restrict__ w,
                          const float* __restrict__ bns,
                          float* __restrict__ yf,
                          __half* __restrict__ ya,
                          int in_row_stride)
{
    const float* xr = x + (size_t)blockIdx.x * in_row_stride * CC;
    int t = threadIdx.x;
    float v0 = xr[t], v1 = xr[t + 256], v2 = xr[t + 512];
    float s = v0 + v1 + v2;
    float q = v0 * v0 + v1 * v1 + v2 * v2;
    #pragma unroll
    for (int o = 16; o; o >>= 1) {
        s += __shfl_xor_sync(0xffffffffu, s, o);
        q += __shfl_xor_sync(0xffffffffu, q, o);
    }
    __shared__ float ss[8], qs[8];
    if ((t & 31) == 0) { ss[t >> 5] = s; qs[t >> 5] = q; }
    __syncthreads();
    float tot = 0.f, totq = 0.f;
    #pragma unroll
    for (int i = 0; i < 8; i++) { tot += ss[i]; totq += qs[i]; }
    float mu   = tot * (1.0f / 768.0f);
    float var  = totq * (1.0f / 768.0f) - mu * mu;
    float rstd = rsqrtf(var + 1e-5f);
    float r0 = (v0 - mu) * rstd * w[t]       + bns[t];
    float r1 = (v1 - mu) * rstd * w[t + 256] + bns[t + 256];
    float r2 = (v2 - mu) * rstd * w[t + 512] + bns[t + 512];
    if (OUTH) {
        size_t base = (size_t)blockIdx.x * CC;
        ya[base + t]       = __float2half_rn(r0);
        ya[base + t + 256] = __float2half_rn(r1);
        ya[base + t + 512] = __float2half_rn(r2);
    } else {
        float* yr = yf + (size_t)blockIdx.x * CC;
        yr[t] = r0; yr[t + 256] = r1; yr[t + 512] = r2;
    }
}

// --------------------------- fused attention ----------------------------------
__global__ __launch_bounds__(256, 2)
void attn_kernel(const float* __restrict__ qkv, __half* __restrict__ oa)
{
    extern __shared__ __half smh[];
    __half* Ks = smh;
    __half* Vs = smh + NN * DK;
    int bh = blockIdx.x;
    int b = bh / HH, h = bh % HH;
    const float* base = qkv + (size_t)b * NN * (3 * CC);

    for (int idx = threadIdx.x; idx < (NN * DK) / 4; idx += 256) {
        int row = idx >> 4, d4 = (idx & 15) << 2;
        float4 kv = *(const float4*)(base + (size_t)row * (3 * CC) +     CC + h * DK + d4);
        float4 vv = *(const float4*)(base + (size_t)row * (3 * CC) + 2 * CC + h * DK + d4);
        *(__half2*)(Ks + row * DK + d4)     = __floats2half2_rn(kv.x, kv.y);
        *(__half2*)(Ks + row * DK + d4 + 2) = __floats2half2_rn(kv.z, kv.w);
        *(__half2*)(Vs + row * DK + d4)     = __floats2half2_rn(vv.x, vv.y);
        *(__half2*)(Vs + row * DK + d4 + 2) = __floats2half2_rn(vv.z, vv.w);
    }
    __syncthreads();

    int grp = threadIdx.x >> 2, sub = threadIdx.x & 3;
    int r0 = blockIdx.y * 128 + grp;
    int r1 = r0 + 64;
    int c0 = (r0 < NN) ? r0 : NN - 1;
    int c1 = (r1 < NN) ? r1 : NN - 1;

    float q0[16], q1[16];
    {
        const float* qp0 = base + (size_t)c0 * (3 * CC) + h * DK + sub * 16;
        const float* qp1 = base + (size_t)c1 * (3 * CC) + h * DK + sub * 16;
        #pragma unroll
        for (int k = 0; k < 16; k += 4) {
            float4 v = *(const float4*)(qp0 + k);
            q0[k] = v.x * 0.125f; q0[k+1] = v.y * 0.125f;
            q0[k+2] = v.z * 0.125f; q0[k+3] = v.w * 0.125f;
            float4 w = *(const float4*)(qp1 + k);
            q1[k] = w.x * 0.125f; q1[k+1] = w.y * 0.125f;
            q1[k+2] = w.z * 0.125f; q1[k+3] = w.w * 0.125f;
        }
    }

    float mx0 = -1e30f, l0 = 0.f, mx1 = -1e30f, l1 = 0.f;
    float acc0[16], acc1[16];
    #pragma unroll
    for (int k = 0; k < 16; k++) { acc0[k] = 0.f; acc1[k] = 0.f; }

    for (int j = 0; j < NN; j++) {
        const __half* kr = Ks + j * DK + sub * 16;
        float kf[16];
        {
            uint4 u0 = *(const uint4*)(kr);
            uint4 u1 = *(const uint4*)(kr + 8);
            const uint32_t* uw = &u0.x;
            #pragma unroll
            for (int e = 0; e < 4; e++) {
                float2 f = __half22float2(*(const __half2*)&uw[e]);
                kf[e * 2] = f.x; kf[e * 2 + 1] = f.y;
            }
            const uint32_t* uw1 = &u1.x;
            #pragma unroll
            for (int e = 0; e < 4; e++) {
                float2 f = __half22float2(*(const __half2*)&uw1[e]);
                kf[8 + e * 2] = f.x; kf[8 + e * 2 + 1] = f.y;
            }
        }
        float s0 = 0.f, s1 = 0.f;
        #pragma unroll
        for (int k = 0; k < 16; k++) { s0 += q0[k] * kf[k]; s1 += q1[k] * kf[k]; }
        s0 += __shfl_xor_sync(0xffffffffu, s0, 1);
        s0 += __shfl_xor_sync(0xffffffffu, s0, 2);
        s1 += __shfl_xor_sync(0xffffffffu, s1, 1);
        s1 += __shfl_xor_sync(0xffffffffu, s1, 2);

        if (s0 > mx0) {
            float cr = __expf(mx0 - s0);
            l0 *= cr;
            #pragma unroll
            for (int k = 0; k < 16; k++) acc0[k] *= cr;
            mx0 = s0;
        }
        float p0 = __expf(s0 - mx0);
        l0 += p0;
        if (s1 > mx1) {
            float cr = __expf(mx1 - s1);
            l1 *= cr;
            #pragma unroll
            for (int k = 0; k < 16; k++) acc1[k] *= cr;
            mx1 = s1;
        }
        float p1 = __expf(s1 - mx1);
        l1 += p1;

        const __half* vr = Vs + j * DK + sub * 16;
        uint4 w0 = *(const uint4*)(vr);
        uint4 w1 = *(const uint4*)(vr + 8);
        const uint32_t* vw0 = &w0.x;
        const uint32_t* vw1 = &w1.x;
        #pragma unroll
        for (int e = 0; e < 4; e++) {
            float2 f = __half22float2(*(const __half2*)&vw0[e]);
            acc0[e*2]   += p0 * f.x; acc0[e*2+1] += p0 * f.y;
            acc1[e*2]   += p1 * f.x; acc1[e*2+1] += p1 * f.y;
            float2 g2 = __half22float2(*(const __half2*)&vw1[e]);
            acc0[8+e*2]   += p0 * g2.x; acc0[8+e*2+1] += p0 * g2.y;
            acc1[8+e*2]   += p1 * g2.x; acc1[8+e*2+1] += p1 * g2.y;
        }
    }

    if (r0 < NN) {
        float inv = 1.0f / l0;
        size_t off = (size_t)(b * NN + r0) * CC + h * DK + sub * 16;
        #pragma unroll
        for (int k = 0; k < 16; k += 2)
            *(__half2*)(oa + off + k) =
                __floats2half2_rn(acc0[k] * inv, acc0[k + 1] * inv);
    }
    if (r1 < NN) {
        float inv = 1.0f / l1;
        size_t off = (size_t)(b * NN + r1) * CC + h * DK + sub * 16;
        #pragma unroll
        for (int k = 0; k < 16; k += 2)
            *(__half2*)(oa + off + k) =
                __floats2half2_rn(acc1[k] * inv, acc1[k + 1] * inv);
    }
}

// --------------------------- small SIMT GEMM (head) ---------------------------
template<bool BIAS>
__global__ void gemm_nt(const float* __restrict__ A, const float* __restrict__ W,
                        const float* __restrict__ bias, float* __restrict__ out,
                        int M, int Nd, int K)
{
    const int BM = 128, BN = 128, BK = 8;
    __shared__ float As[BK][BM + 4];
    __shared__ float Ws[BK][BN + 4];
    int t = threadIdx.x, tx = t & 15, ty = t >> 4;
    int m0 = blockIdx.x * BM, n0 = blockIdx.y * BN;
    int lrow = t >> 1, lk = (t & 1) * 4;
    float acc[8][8];
    #pragma unroll
    for (int i = 0; i < 8; i++)
        #pragma unroll
        for (int j = 0; j < 8; j++) acc[i][j] = 0.f;
    for (int k0 = 0; k0 < K; k0 += BK) {
        int gm = m0 + lrow;
        float4 va = (gm < M) ? *(const float4*)(A + (size_t)gm * K + k0 + lk)
                             : make_float4(0,0,0,0);
        As[lk+0][lrow]=va.x; As[lk+1][lrow]=va.y; As[lk+2][lrow]=va.z; As[lk+3][lrow]=va.w;
        int gn = n0 + lrow;
        float4 vw = (gn < Nd) ? *(const float4*)(W + (size_t)gn * K + k0 + lk)
                              : make_float4(0,0,0,0);
        Ws[lk+0][lrow]=vw.x; Ws[lk+1][lrow]=vw.y; Ws[lk+2][lrow]=vw.z; Ws[lk+3][lrow]=vw.w;
        __syncthreads();
        #pragma unroll
        for (int k = 0; k < BK; k++) {
            float ra[8], rb[8];
            *(float4*)(ra)   = *(const float4*)&As[k][ty*8];
            *(float4*)(ra+4) = *(const float4*)&As[k][ty*8+4];
            *(float4*)(rb)   = *(const float4*)&Ws[k][tx*8];
            *(float4*)(rb+4) = *(const float4*)&Ws[k][tx*8+4];
            #pragma unroll
            for (int i = 0; i < 8; i++)
                #pragma unroll
                for (int j = 0; j < 8; j++) acc[i][j] += ra[i] * rb[j];
        }
        __syncthreads();
    }
    #pragma unroll
    for (int i = 0; i < 8; i++) {
        int gm = m0 + ty * 8 + i;
        if (gm >= M) continue;
        #pragma unroll
        for (int j = 0; j < 8; j++) {
            int gn = n0 + tx * 8 + j;
            if (gn >= Nd) continue;
            float v = acc[i][j];
            if (BIAS) v += bias[gn];
            out[(size_t)gm * Nd + gn] = v;
        }
    }
}

// ---------------------------------------------------------------------------
extern "C" void kernel_launch(void* const* d_in, const int* in_sizes, int n_in,
                              void* d_out, int out_size)
{
    const float* x      = (const float*)d_in[0];
    const float* cls    = (const float*)d_in[1];
    const float* qkv_w  = (const float*)d_in[2];
    const float* proj_w = (const float*)d_in[3];
    const float* proj_b = (const float*)d_in[4];
    const float* ln1_w  = (const float*)d_in[5];
    const float* ln1_b  = (const float*)d_in[6];
    const float* ln2_w  = (const float*)d_in[7];
    const float* ln2_b  = (const float*)d_in[8];
    const float* fc1_w  = (const float*)d_in[9];
    const float* fc1_b  = (const float*)d_in[10];
    const float* fc2_w  = (const float*)d_in[11];
    const float* fc2_b  = (const float*)d_in[12];
    const float* norm_w = (const float*)d_in[13];
    const float* norm_b = (const float*)d_in[14];
    const float* head_w = (const float*)d_in[15];
    const float* head_b = (const float*)d_in[16];
    float* out = (float*)d_out;

    float *ph, *pqkv, *pcls;
    __half *pya, *poa, *pma;
    __half *pwqh, *pwql, *pwph, *pwpl, *pw1h, *pw2h;
    cudaGetSymbolAddress((void**)&ph,   g_h);
    cudaGetSymbolAddress((void**)&pqkv, g_qkv);
    cudaGetSymbolAddress((void**)&pcls, g_cls);
    cudaGetSymbolAddress((void**)&pya, g_ya);
    cudaGetSymbolAddress((void**)&poa, g_oa);
    cudaGetSymbolAddress((void**)&pma, g_ma);
    cudaGetSymbolAddress((void**)&pwqh, g_wqh); cudaGetSymbolAddress((void**)&pwql, g_wql);
    cudaGetSymbolAddress((void**)&pwph, g_wph); cudaGetSymbolAddress((void**)&pwpl, g_wpl);
    cudaGetSymbolAddress((void**)&pw1h, g_w1h);
    cudaGetSymbolAddress((void**)&pw2h, g_w2h);

    cudaFuncSetAttribute(attn_kernel,
                         cudaFuncAttributeMaxDynamicSharedMemorySize, ATT_SMEM);
    cudaFuncSetAttribute(gemm_hf<false,false,false,false,true>,
                         cudaFuncAttributeMaxDynamicSharedMemorySize, GB_SMEM);
    cudaFuncSetAttribute(gemm_hf<true,false,true,false,true>,
                         cudaFuncAttributeMaxDynamicSharedMemorySize, GB_SMEM);
    cudaFuncSetAttribute(gemm_hf<true,true,false,true,false>,
                         cudaFuncAttributeMaxDynamicSharedMemorySize, GB_SMEM);
    cudaFuncSetAttribute(gemm_hf<true,false,true,false,false>,
                         cudaFuncAttributeMaxDynamicSharedMemorySize, GB_SMEM);

    const int MTT = MP / 128;  // 99

    // Launch order keeps the first QKV gemm at launch #4 for the profiler.
    conv_kernel<<<1184, 256>>>((const float4*)qkv_w, (uint2*)pwqh, (uint2*)pwql, W_QKV/4);
    embed_kernel<<<MP, 256>>>(x, cls, ph);
    ln_kernel<true><<<TT, 256>>>(ph, ln1_w, ln1_b, nullptr, pya, 1);
    gemm_hf<false,false,false,false,true><<<dim3((3*CC)/128, MTT), 256, GB_SMEM>>>(
        pya, pwqh, pwql, nullptr, nullptr, pqkv, nullptr, MP, 3*CC, CC);
    conv_kernel<<<1184, 256>>>((const float4*)proj_w, (uint2*)pwph, (uint2*)pwpl, W_PRJ/4);
    conv1_kernel<<<1184, 256>>>((const float4*)fc1_w, (uint2*)pw1h, W_FC1/4);
    conv1_kernel<<<1184, 256>>>((const float4*)fc2_w, (uint2*)pw2h, W_FC2/4);

    for (int d = 0; d < NL; d++) {
        const __half* qwh = pwqh + (size_t)d * 3 * CC * CC;
        const __half* qwl = pwql + (size_t)d * 3 * CC * CC;
        const __half* pwh = pwph + (size_t)d * CC * CC;
        const __half* pwl = pwpl + (size_t)d * CC * CC;
        const __half* w1h = pw1h + (size_t)d * FF * CC;
        const __half* w2h = pw2h + (size_t)d * CC * FF;
        const float* pb  = proj_b + (size_t)d * CC;
        const float* l2w = ln2_w  + (size_t)d * CC;
        const float* l2b = ln2_b  + (size_t)d * CC;
        const float* f1b = fc1_b  + (size_t)d * FF;
        const float* f2b = fc2_b  + (size_t)d * CC;

        if (d > 0) {
            const float* l1w = ln1_w + (size_t)d * CC;
            const float* l1b = ln1_b + (size_t)d * CC;
            ln_kernel<true><<<TT, 256>>>(ph, l1w, l1b, nullptr, pya, 1);
            gemm_hf<false,false,false,false,true><<<dim3((3*CC)/128, MTT), 256, GB_SMEM>>>(
                pya, qwh, qwl, nullptr, nullptr, pqkv, nullptr, MP, 3*CC, CC);
        }
        attn_kernel<<<dim3(BB*HH, 2), 256, ATT_SMEM>>>(pqkv, poa);
        gemm_hf<true,false,true,false,true><<<dim3(CC/128, MTT), 256, GB_SMEM>>>(
            poa, pwh, pwl, pb, ph, ph, nullptr, MP, CC, CC);
        ln_kernel<true><<<TT, 256>>>(ph, l2w, l2b, nullptr, pya, 1);
        gemm_hf<true,true,false,true,false><<<dim3(FF/128, MTT), 256, GB_SMEM>>>(
            pya, w1h, nullptr, f1b, nullptr, nullptr, pma, MP, FF, CC);
        gemm_hf<true,false,true,false,false><<<dim3(CC/128, MTT), 256, GB_SMEM>>>(
            pma, w2h, nullptr, f2b, ph, ph, nullptr, MP, CC, FF);
    }

    ln_kernel<false><<<BB, 256>>>(ph, norm_w, norm_b, pcls, nullptr, NN);
    gemm_nt<true><<<dim3(1, (VV + 127) / 128), 256>>>(
        pcls, head_w, head_b, out, BB, VV, CC);
}